// round 6
// baseline (speedup 1.0000x reference)
#include <cuda_runtime.h>
#include <cuda_fp16.h>
#include <math.h>
#include <stdint.h>

// Problem constants (fixed by the dataset)
#define BB 2
#define NN 50000
#define DD 128
#define EE 500000
#define RR 500
#define ROWS (BB * NN)          // 100000 node-rows

// Scratch (static device globals — no runtime allocation)
__device__ __align__(16) __half   g_p[ROWS * DD];    // (h@msg_W)*sig(h@gate_W) fp16, 25.6MB
__device__ __align__(16) __half   g_rel[RR * DD];    // rel_emb fp16, 128KB (L1-resident)
__device__ __align__(16) float    g_agg[ROWS * DD];  // aggregated messages, 51.2MB
__device__ __align__(16) uint32_t g_Bp_msg[16 * 16 * 32 * 2];
__device__ __align__(16) uint32_t g_Bp_gate[16 * 16 * 32 * 2];
__device__ __align__(16) uint32_t g_Bp_upd[32 * 16 * 32 * 2];
// counting-sort state
__device__ int  g_cnt[NN];
__device__ int  g_start[NN];
__device__ int  g_cursor[NN];
__device__ __align__(8) int2 g_edge[EE];   // (src, rel) sorted by tgt

// ---------------------------------------------------------------------------
// tf32 mma helpers
// ---------------------------------------------------------------------------
__device__ __forceinline__ uint32_t f2tf32(float x) {
    uint32_t r;
    asm("cvt.rna.tf32.f32 %0, %1;" : "=r"(r) : "f"(x));
    return r;
}

__device__ __forceinline__ void mma_tf32(float c[4], const uint32_t a[4],
                                         const uint32_t b[2]) {
    asm volatile(
        "mma.sync.aligned.m16n8k8.row.col.f32.tf32.tf32.f32 "
        "{%0,%1,%2,%3}, {%4,%5,%6,%7}, {%8,%9}, {%0,%1,%2,%3};"
        : "+f"(c[0]), "+f"(c[1]), "+f"(c[2]), "+f"(c[3])
        : "r"(a[0]), "r"(a[1]), "r"(a[2]), "r"(a[3]), "r"(b[0]), "r"(b[1]));
}

#define ASH_WORDS (64 * 132)
#define GEMM_SMEM ((ASH_WORDS + 16384) * 4)     // 99328 B -> 2 CTAs/SM

// ---------------------------------------------------------------------------
// Setup: permute weights into mma B-fragment order; convert rel_emb to fp16.
// ---------------------------------------------------------------------------
__global__ void permute_W_kernel(const float* __restrict__ msg_W,
                                 const float* __restrict__ gate_W,
                                 const float* __restrict__ upd_W,
                                 const float* __restrict__ rel_emb)
{
    const int job = blockIdx.x;
    const int tid = threadIdx.x;

    if (job == 4) {   // rel_emb -> fp16
        for (int i = tid; i < RR * DD / 2; i += 256) {
            float2 v = ((const float2*)rel_emb)[i];
            ((__half2*)g_rel)[i] = __floats2half2_rn(v.x, v.y);
        }
        return;
    }

    const float* src;
    uint32_t* dst;
    if (job == 0)      { src = msg_W;  dst = g_Bp_msg; }
    else if (job == 1) { src = gate_W; dst = g_Bp_gate; }
    else               { src = upd_W + (job - 2) * 128 * 128;
                         dst = g_Bp_upd + (job - 2) * 16384; }

    const float4* W4 = (const float4*)src;
    for (int i = tid; i < 128 * 32; i += 256) {
        int k = i >> 5, n4 = (i & 31) * 4;
        float4 v = W4[i];
        float vv[4] = {v.x, v.y, v.z, v.w};
        int kt = k >> 3, slot = (k >> 2) & 1, kl = k & 3;
#pragma unroll
        for (int j = 0; j < 4; j++) {
            int nn = n4 + j;
            int lane = ((nn & 7) << 2) | kl;
            dst[((((kt << 4) | (nn >> 3)) << 5) | lane) * 2 + slot] = f2tf32(vv[j]);
        }
    }
}

// ---------------------------------------------------------------------------
// Counting sort of edges by target node
// ---------------------------------------------------------------------------
__global__ void hist_kernel(const int* __restrict__ etgt)
{
    int e = blockIdx.x * 256 + threadIdx.x;
    if (e < EE) atomicAdd(&g_cnt[etgt[e]], 1);
}

__global__ __launch_bounds__(1024) void scan_kernel()
{
    __shared__ int ps[1024];
    const int t = threadIdx.x;
    const int CH = 49;                       // 1024*49 >= 50000
    int lo = t * CH, hi = lo + CH;
    if (hi > NN) hi = NN;
    int s = 0;
    for (int i = lo; i < hi; i++) s += g_cnt[i];
    ps[t] = s;
    __syncthreads();
    for (int off = 1; off < 1024; off <<= 1) {
        int v = (t >= off) ? ps[t - off] : 0;
        __syncthreads();
        ps[t] += v;
        __syncthreads();
    }
    int run = (t == 0) ? 0 : ps[t - 1];
    for (int i = lo; i < hi; i++) {
        g_start[i] = run;
        g_cursor[i] = run;
        run += g_cnt[i];
    }
}

__global__ void permute_edges_kernel(const int* __restrict__ esrc,
                                     const int* __restrict__ etgt,
                                     const int* __restrict__ erel)
{
    int e = blockIdx.x * 256 + threadIdx.x;
    if (e >= EE) return;
    int t = etgt[e];
    int pos = atomicAdd(&g_cursor[t], 1);
    g_edge[pos] = make_int2(esrc[e], erel[e]);
}

// ---------------------------------------------------------------------------
// Mainloop: warp tile 32x32 over K=128 (16 k-steps of 8).
// ---------------------------------------------------------------------------
__device__ __forceinline__ void mma_mainloop(
    const float* __restrict__ A0, const uint32_t* __restrict__ Bw,
    float (&acc)[2][4][4])
{
#pragma unroll
    for (int ks = 0; ks < 16; ks++) {
        uint32_t af[2][4];
#pragma unroll
        for (int mt = 0; mt < 2; mt++) {
            const float* ap = A0 + mt * 2112 + ks * 8;   // 2112 = 16*132
            af[mt][0] = __float_as_uint(ap[0]);
            af[mt][1] = __float_as_uint(ap[1056]);        // +8 rows
            af[mt][2] = __float_as_uint(ap[4]);           // +4 k
            af[mt][3] = __float_as_uint(ap[1060]);
        }
#pragma unroll
        for (int nt = 0; nt < 4; nt++) {
            uint2 bv = *(const uint2*)(Bw + ks * 1024 + nt * 64);
            uint32_t bf[2] = {bv.x, bv.y};
            mma_tf32(acc[0][nt], af[0], bf);
            mma_tf32(acc[1][nt], af[1], bf);
        }
    }
}

__device__ __forceinline__ void fill_A(float* Ash, const float4* __restrict__ src4,
                                       int m0, int tid)
{
#pragma unroll
    for (int it = 0; it < 8; it++) {
        int i = tid + it * 256;
        int m = i >> 5, c = i & 31;
        int row = m0 + m;
        float4 v = (row < ROWS) ? src4[row * 32 + c]
                                : make_float4(0.f, 0.f, 0.f, 0.f);
        uint4 t;
        t.x = f2tf32(v.x); t.y = f2tf32(v.y);
        t.z = f2tf32(v.z); t.w = f2tf32(v.w);
        *(uint4*)&Ash[m * 132 + c * 4] = t;
    }
}

// ---------------------------------------------------------------------------
// Kernel 1: p = (h @ msg_W) * sigmoid(h @ gate_W)  -> fp16
// ---------------------------------------------------------------------------
__global__ __launch_bounds__(256, 2) void node_p_mma(const float* __restrict__ h)
{
    extern __shared__ uint32_t sh[];
    float*    Ash = (float*)sh;       // [64][132]
    uint32_t* Bs  = sh + ASH_WORDS;   // 16384 words

    const int tid  = threadIdx.x;
    const int m0   = blockIdx.x * 64;
    const int lane = tid & 31, wid = tid >> 5;
    const int wm = wid >> 2, wn = wid & 3;

    fill_A(Ash, (const float4*)h, m0, tid);

    float accM[2][4][4], accG[2][4][4];
#pragma unroll
    for (int mt = 0; mt < 2; mt++)
#pragma unroll
        for (int nt = 0; nt < 4; nt++)
#pragma unroll
            for (int q = 0; q < 4; q++) { accM[mt][nt][q] = 0.f; accG[mt][nt][q] = 0.f; }

    const float*    A0 = Ash + (wm * 32 + (lane >> 2)) * 132 + (lane & 3);
    const uint32_t* Bw = Bs + ((wn * 4) << 6) + lane * 2;

    {   // Stage 0: msg_W
        const uint4* src = (const uint4*)g_Bp_msg;
#pragma unroll
        for (int it = 0; it < 16; it++) ((uint4*)Bs)[tid + it * 256] = src[tid + it * 256];
        __syncthreads();
        mma_mainloop(A0, Bw, accM);
    }
    {   // Stage 1: gate_W
        __syncthreads();
        const uint4* src = (const uint4*)g_Bp_gate;
#pragma unroll
        for (int it = 0; it < 16; it++) ((uint4*)Bs)[tid + it * 256] = src[tid + it * 256];
        __syncthreads();
        mma_mainloop(A0, Bw, accG);
    }

    // Epilogue: p = accM * sigmoid(accG) -> fp16 smem stage (stride 68 half2)
    __syncthreads();
    __half2* Psh = (__half2*)sh;            // [64][68 half2]
    {
        const int r = lane >> 2;
        const int colh = (lane & 3);        // + wn*16 + nt*4
#pragma unroll
        for (int mt = 0; mt < 2; mt++)
#pragma unroll
            for (int nt = 0; nt < 4; nt++) {
                int rr = wm * 32 + mt * 16 + r;
                int ch = wn * 16 + nt * 4 + colh;
                float s0 = 1.f / (1.f + __expf(-accG[mt][nt][0]));
                float s1 = 1.f / (1.f + __expf(-accG[mt][nt][1]));
                float s2 = 1.f / (1.f + __expf(-accG[mt][nt][2]));
                float s3 = 1.f / (1.f + __expf(-accG[mt][nt][3]));
                Psh[rr * 68 + ch]       = __floats2half2_rn(accM[mt][nt][0] * s0,
                                                            accM[mt][nt][1] * s1);
                Psh[(rr + 8) * 68 + ch] = __floats2half2_rn(accM[mt][nt][2] * s2,
                                                            accM[mt][nt][3] * s3);
            }
    }
    __syncthreads();
    // Coalesced out: 64 rows x 16 uint4 (256B/row)
#pragma unroll
    for (int it = 0; it < 4; it++) {
        int i = tid + it * 256;
        int m = i >> 4, c = i & 15;
        int row = m0 + m;
        if (row < ROWS)
            ((uint4*)g_p)[row * 16 + c] = *(uint4*)&Psh[m * 68 + c * 4];
    }
}

// ---------------------------------------------------------------------------
// Kernel 2: aggregation — one warp per node, both batches, register acc.
//   agg[b, n] = sum_{e: tgt=n} p[b, src_e] * rel[rel_e]
// ---------------------------------------------------------------------------
__global__ __launch_bounds__(256) void agg_kernel()
{
    const int warp = (blockIdx.x * 256 + threadIdx.x) >> 5;
    const int lane = threadIdx.x & 31;
    if (warp >= NN) return;

    const int start = g_start[warp];
    const int deg   = g_cnt[warp];

    const __half2* P  = (const __half2*)g_p;    // [ROWS][64]
    const __half2* RL = (const __half2*)g_rel;  // [RR][64]

    float4 a0 = make_float4(0.f, 0.f, 0.f, 0.f);
    float4 a1 = make_float4(0.f, 0.f, 0.f, 0.f);

    for (int i = 0; i < deg; i++) {
        int2 e = g_edge[start + i];             // (src, rel), warp-broadcast
        float2 r0 = __half22float2(RL[e.y * 64 + lane * 2]);
        float2 r1 = __half22float2(RL[e.y * 64 + lane * 2 + 1]);

        float2 p0 = __half22float2(P[e.x * 64 + lane * 2]);
        float2 p1 = __half22float2(P[e.x * 64 + lane * 2 + 1]);
        a0.x += p0.x * r0.x; a0.y += p0.y * r0.y;
        a0.z += p1.x * r1.x; a0.w += p1.y * r1.y;

        float2 q0 = __half22float2(P[(NN + e.x) * 64 + lane * 2]);
        float2 q1 = __half22float2(P[(NN + e.x) * 64 + lane * 2 + 1]);
        a1.x += q0.x * r0.x; a1.y += q0.y * r0.y;
        a1.z += q1.x * r1.x; a1.w += q1.y * r1.y;
    }

    ((float4*)g_agg)[warp * 32 + lane]        = a0;   // b = 0
    ((float4*)g_agg)[(NN + warp) * 32 + lane] = a1;   // b = 1
}

// ---------------------------------------------------------------------------
// Kernel 3: upd = [h | agg] @ update_W + b ; x = h + relu(upd) ; out = LN(x)
// ---------------------------------------------------------------------------
__global__ __launch_bounds__(256, 2) void update_ln_mma(
    const float* __restrict__ h,
    const float* __restrict__ update_b,
    const float* __restrict__ ln_gamma,
    const float* __restrict__ ln_beta,
    float* __restrict__ out)
{
    extern __shared__ uint32_t sh[];
    float*    Ash = (float*)sh;       // [64][132] (A stage, then X for LN)
    uint32_t* Bs  = sh + ASH_WORDS;   // 16384 words

    const int tid  = threadIdx.x;
    const int m0   = blockIdx.x * 64;
    const int lane = tid & 31, wid = tid >> 5;
    const int wm = wid >> 2, wn = wid & 3;

    float acc[2][4][4];
#pragma unroll
    for (int mt = 0; mt < 2; mt++)
#pragma unroll
        for (int nt = 0; nt < 4; nt++)
#pragma unroll
            for (int q = 0; q < 4; q++) acc[mt][nt][q] = 0.f;

    const float*    A0 = Ash + (wm * 32 + (lane >> 2)) * 132 + (lane & 3);
    const uint32_t* Bw = Bs + ((wn * 4) << 6) + lane * 2;

#pragma unroll
    for (int s = 0; s < 2; s++) {
        if (s) __syncthreads();
        const uint4* bsrc = (const uint4*)g_Bp_upd + s * 4096;
#pragma unroll
        for (int it = 0; it < 16; it++) ((uint4*)Bs)[tid + it * 256] = bsrc[tid + it * 256];
        fill_A(Ash, (const float4*)(s ? g_agg : h), m0, tid);
        __syncthreads();
        mma_mainloop(A0, Bw, acc);
    }

    // Epilogue: X = relu(acc + bias) -> Ash (residual added in LN pass)
    __syncthreads();
    {
        const int r = lane >> 2, c2 = (lane & 3) * 2;
#pragma unroll
        for (int mt = 0; mt < 2; mt++)
#pragma unroll
            for (int nt = 0; nt < 4; nt++) {
                int rr  = wm * 32 + mt * 16 + r;
                int col = wn * 32 + nt * 8 + c2;
                float b0 = __ldg(&update_b[col]);
                float b1 = __ldg(&update_b[col + 1]);
                float v0 = fmaxf(acc[mt][nt][0] + b0, 0.f);
                float v1 = fmaxf(acc[mt][nt][1] + b1, 0.f);
                float v2 = fmaxf(acc[mt][nt][2] + b0, 0.f);
                float v3 = fmaxf(acc[mt][nt][3] + b1, 0.f);
                *(float2*)&Ash[rr * 132 + col]       = make_float2(v0, v1);
                *(float2*)&Ash[(rr + 8) * 132 + col] = make_float2(v2, v3);
            }
    }
    __syncthreads();

    // LayerNorm: 8 warps x 8 rows; residual h added here (coalesced read)
    {
        const float4 gm = ((const float4*)ln_gamma)[lane];
        const float4 bt = ((const float4*)ln_beta)[lane];
        const float4* h4 = (const float4*)h;
        for (int rr = wid; rr < 64; rr += 8) {
            int row = m0 + rr;
            if (row >= ROWS) continue;
            float4 xv = *(const float4*)&Ash[rr * 132 + lane * 4];
            float4 hv = h4[row * 32 + lane];
            float4 x = make_float4(xv.x + hv.x, xv.y + hv.y,
                                   xv.z + hv.z, xv.w + hv.w);
            float sum = x.x + x.y + x.z + x.w;
            float sq  = x.x * x.x + x.y * x.y + x.z * x.z + x.w * x.w;
#pragma unroll
            for (int off = 16; off; off >>= 1) {
                sum += __shfl_xor_sync(0xffffffffu, sum, off);
                sq  += __shfl_xor_sync(0xffffffffu, sq, off);
            }
            float mu  = sum * (1.f / 128.f);
            float var = sq * (1.f / 128.f) - mu * mu;
            float inv = rsqrtf(var + 1e-5f);
            float4 o;
            o.x = (x.x - mu) * inv * gm.x + bt.x;
            o.y = (x.y - mu) * inv * gm.y + bt.y;
            o.z = (x.z - mu) * inv * gm.z + bt.z;
            o.w = (x.w - mu) * inv * gm.w + bt.w;
            ((float4*)out)[row * 32 + lane] = o;
        }
    }
}

// ---------------------------------------------------------------------------
extern "C" void kernel_launch(void* const* d_in, const int* in_sizes, int n_in,
                              void* d_out, int out_size)
{
    const float* h        = (const float*)d_in[0];
    const int*   esrc     = (const int*)d_in[1];
    const int*   etgt     = (const int*)d_in[2];
    const int*   erel     = (const int*)d_in[3];
    // d_in[4] = nE (== NN, unused)
    const float* msg_W    = (const float*)d_in[5];
    const float* rel_emb  = (const float*)d_in[6];
    const float* gate_W   = (const float*)d_in[7];
    const float* update_W = (const float*)d_in[8];
    const float* update_b = (const float*)d_in[9];
    const float* gamma    = (const float*)d_in[10];
    const float* beta     = (const float*)d_in[11];
    float*       out      = (float*)d_out;

    cudaFuncSetAttribute(node_p_mma,
                         cudaFuncAttributeMaxDynamicSharedMemorySize, GEMM_SMEM);
    cudaFuncSetAttribute(update_ln_mma,
                         cudaFuncAttributeMaxDynamicSharedMemorySize, GEMM_SMEM);

    // Zero histogram counters (200KB)
    void* cnt_ptr = nullptr;
    cudaGetSymbolAddress(&cnt_ptr, g_cnt);
    cudaMemsetAsync(cnt_ptr, 0, sizeof(int) * NN, 0);

    permute_W_kernel<<<5, 256>>>(msg_W, gate_W, update_W, rel_emb);

    const int eblocks = (EE + 255) / 256;   // 1954
    hist_kernel<<<eblocks, 256>>>(etgt);
    scan_kernel<<<1, 1024>>>();
    permute_edges_kernel<<<eblocks, 256>>>(esrc, etgt, erel);

    const int mtiles = (ROWS + 63) / 64;    // 1563
    node_p_mma<<<mtiles, 256, GEMM_SMEM>>>(h);

    agg_kernel<<<(NN * 32 + 255) / 256, 256>>>();

    update_ln_mma<<<mtiles, 256, GEMM_SMEM>>>(h, update_b, gamma, beta, out);
}